// round 14
// baseline (speedup 1.0000x reference)
#include <cuda_runtime.h>
#include <math.h>
#include <cstdint>

// ---------------- problem constants ----------------
#define N_TOT   65536      // B*H*W
#define K_CB    512
#define C_DIM   64
#define B_DIM   64
#define HW      1024

#define TM      64         // rows per tile (8 warps x 8 rows)
#define THREADS 256
#define NWARP   8
#define NTILES  1024
#define NCTAS   152        // persistent, 1 CTA/SM
#define WROW    514        // wT row stride (floats)

// output layout (floats), concatenation of the reference tuple
#define Q_OFF     0ULL
#define LOSS_OFF  4194304ULL
#define PERP_OFF  4194368ULL
#define ENC_OFF   4194369ULL
#define EIDX_OFF  37748801ULL
#define DIST_OFF  37814337ULL
#define OUT_TOTAL 71368769

// smem layout (float indices)
#define SM_WT   0                      // wT[64][514] = 32896 floats
#define SM_XW   32896                  // per-warp x slices: 8 warps x 2 bufs x 512 = 8192
#define SM_WN   (SM_XW + 8192)         // wnorm[512]
#define SM_RED  (SM_WN + 512)          // float red[512] (finish only)
#define SM_TOTF (SM_RED + 512)
#define SMEM_BYTES (SM_TOTF * 4)       // ~168 KB -> 1 CTA/SM

__device__ float g_lp[NTILES * NWARP]; // per (tile, warp) loss partial
__device__ int   g_hist[K_CB];         // zero at load; last CTA re-zeroes each launch
__device__ int   g_done;               // arrival ticket; last CTA resets

typedef unsigned long long ull;

// ---------------- helpers ----------------
__device__ __forceinline__ ull pack2(float x) {
    ull r; asm("mov.b64 %0, {%1, %1};" : "=l"(r) : "f"(x)); return r;
}
__device__ __forceinline__ void fma2(ull &d, ull a, ull b) {
    asm("fma.rn.f32x2 %0, %1, %2, %3;" : "=l"(d) : "l"(a), "l"(b), "l"(d));
}
__device__ __forceinline__ void unpack2(ull v, float &lo, float &hi) {
    asm("mov.b64 {%0, %1}, %2;" : "=f"(lo), "=f"(hi) : "l"(v));
}
__device__ __forceinline__ uint32_t smem_u32(const void* p) {
    uint32_t a;
    asm("{ .reg .u64 t; cvta.to.shared.u64 t, %1; cvt.u32.u64 %0, t; }" : "=r"(a) : "l"(p));
    return a;
}
#define CP_ASYNC16(sa, gp) asm volatile("cp.async.cg.shared.global [%0], [%1], 16;" :: "r"(sa), "l"(gp))
#define CP_COMMIT()        asm volatile("cp.async.commit_group;" ::: "memory")
#define CP_WAIT1()         asm volatile("cp.async.wait_group 1;" ::: "memory")
#define CP_WAIT0()         asm volatile("cp.async.wait_group 0;" ::: "memory")

// ---------------- single persistent kernel, free-running warps, 8 rows/warp ----------------
extern "C" __global__ void __launch_bounds__(THREADS, 1)
vq_all(const float* __restrict__ inputs, const float* __restrict__ weight,
       float* __restrict__ out)
{
    extern __shared__ float smem[];
    float* wT    = smem + SM_WT;       // wT[c][k]
    float* wnorm = smem + SM_WN;
    float* red   = smem + SM_RED;

    const int tid  = threadIdx.x;
    const int warp = tid >> 5;         // warp owns rows 8*warp .. 8*warp+7 of every tile
    const int lane = tid & 31;
    const int cta  = blockIdx.x;

    float* xw_base = smem + SM_XW + warp * 1024;        // 2 slices x 512 floats: [c][8]
    const uint32_t xw_sa = smem_u32(xw_base);

    // per-thread cp.async channels: this thread copies c = lane and c = lane+32 (32B each)
    const int c0 = lane, c1 = lane + 32;

    // ---- prefetch first tile's slice into buf 0 ----
    {
        const int t0 = cta;
        const float* src = inputs + (size_t)(t0 >> 4) * (C_DIM * HW)
                         + (t0 & 15) * 64 + 8 * warp;
        CP_ASYNC16(xw_sa + (uint32_t)(c0 * 8) * 4,       src + (size_t)c0 * HW);
        CP_ASYNC16(xw_sa + (uint32_t)(c0 * 8 + 4) * 4,   src + (size_t)c0 * HW + 4);
        CP_ASYNC16(xw_sa + (uint32_t)(c1 * 8) * 4,       src + (size_t)c1 * HW);
        CP_ASYNC16(xw_sa + (uint32_t)(c1 * 8 + 4) * 4,   src + (size_t)c1 * HW + 4);
        CP_COMMIT();
    }

    // ---- one-time: weight transpose + wnorm (the only CTA barriers) ----
    for (int i = tid; i < K_CB * C_DIM; i += THREADS) {
        int k = i >> 6, c = i & 63;
        wT[c * WROW + k] = weight[i];
    }
    __syncthreads();
    for (int k = tid; k < K_CB; k += THREADS) {
        float s = 0.f;
        #pragma unroll
        for (int c = 0; c < C_DIM; c++) { float w = wT[c * WROW + k]; s = fmaf(w, w, s); }
        wnorm[k] = s;
    }
    __syncthreads();

    // ---- per-warp persistent tile loop (no CTA barriers inside) ----
    int buf = 0;
    for (int t = cta; t < NTILES; t += NCTAS) {
        // prefetch next tile's slice into the other buffer
        {
            int tn = t + NCTAS; if (tn >= NTILES) tn = 0;
            const float* src = inputs + (size_t)(tn >> 4) * (C_DIM * HW)
                             + (tn & 15) * 64 + 8 * warp;
            uint32_t dst = xw_sa + (uint32_t)((buf ^ 1) * 512) * 4;
            CP_ASYNC16(dst + (uint32_t)(c0 * 8) * 4,     src + (size_t)c0 * HW);
            CP_ASYNC16(dst + (uint32_t)(c0 * 8 + 4) * 4, src + (size_t)c0 * HW + 4);
            CP_ASYNC16(dst + (uint32_t)(c1 * 8) * 4,     src + (size_t)c1 * HW);
            CP_ASYNC16(dst + (uint32_t)(c1 * 8 + 4) * 4, src + (size_t)c1 * HW + 4);
            CP_COMMIT();
        }
        CP_WAIT1();                    // current buffer's copies done (this thread)
        __syncwarp();                  // all lanes' copies visible warp-wide

        const float* slice = xw_base + buf * 512;   // [c][8] floats

        // xnorm for own rows: lane r (<8) computes row r (sequential fmaf rounding)
        float xn_own = 0.f;
        if (lane < 8) {
            #pragma unroll
            for (int c = 0; c < C_DIM; c++) {
                float x = slice[c * 8 + lane];
                xn_own = fmaf(x, x, xn_own);
            }
        }

        // ---- mainloop: 8 rows x 16 codes per lane; codes k = 2*lane + 64*j ----
        ull acc[8][8];
        #pragma unroll
        for (int r = 0; r < 8; r++)
            #pragma unroll
            for (int j = 0; j < 8; j++) acc[r][j] = 0ULL;

        const ull* bbase = (const ull*)(wT + 2 * lane);

        #pragma unroll 2
        for (int c = 0; c < C_DIM; c++) {
            const float4 a0 = *(const float4*)(slice + c * 8);       // broadcast rows 0-3
            const float4 a1 = *(const float4*)(slice + c * 8 + 4);   // broadcast rows 4-7
            ull aa[8];
            aa[0] = pack2(a0.x); aa[1] = pack2(a0.y); aa[2] = pack2(a0.z); aa[3] = pack2(a0.w);
            aa[4] = pack2(a1.x); aa[5] = pack2(a1.y); aa[6] = pack2(a1.z); aa[7] = pack2(a1.w);
            const ull* bp = bbase + (size_t)c * (WROW / 2);
            ull bb[8];
            #pragma unroll
            for (int j = 0; j < 8; j++) bb[j] = bp[32 * j];          // conflict-free LDS.64
            #pragma unroll
            for (int r = 0; r < 8; r++)
                #pragma unroll
                for (int j = 0; j < 8; j++) fma2(acc[r][j], aa[r], bb[j]);
        }

        const int n0   = t * TM + 8 * warp;       // first row owned by this warp
        const int bimg = t >> 4;
        const int p0   = (t & 15) * 64 + 8 * warp;

        // ---- epilogue: distances (reference rounding) + full-K warp argmin ----
        const float INF = __int_as_float(0x7f800000);
        int bi_r[8];
        #pragma unroll
        for (int r = 0; r < 8; r++) {
            const int n = n0 + r;
            const float xn = __shfl_sync(0xffffffffu, xn_own, r);

            float best = INF; int bidx = 0;
            float* dptr = out + DIST_OFF + (size_t)n * K_CB;
            #pragma unroll
            for (int j = 0; j < 8; j++) {
                float zlo, zhi; unpack2(acc[r][j], zlo, zhi);
                const int k0 = 2 * lane + 64 * j;
                const float2 wn2 = *(const float2*)(wnorm + k0);  // LDS.64 aligned
                float dlo = (xn + wn2.x) - 2.0f * zlo;
                float dhi = (xn + wn2.y) - 2.0f * zhi;
                __stcs(dptr + k0,     dlo);                       // coalesced pairs
                __stcs(dptr + k0 + 1, dhi);
                if (dlo < best) { best = dlo; bidx = k0; }        // ascending k, strict '<'
                if (dhi < best) { best = dhi; bidx = k0 + 1; }    // -> lowest index on ties
            }
            #pragma unroll
            for (int off = 16; off > 0; off >>= 1) {
                float ob = __shfl_xor_sync(0xffffffffu, best, off);
                int   oi = __shfl_xor_sync(0xffffffffu, bidx, off);
                if (ob < best || (ob == best && oi < bidx)) { best = ob; bidx = oi; }
            }
            bi_r[r] = bidx;                                      // all lanes agree
            if (lane == 0) {
                out[EIDX_OFF + (size_t)n] = (float)bidx;
                atomicAdd(&g_hist[bidx], 1);                     // order-independent
            }
        }

        // ---- encodings one-hot for own 8 rows: float4 interior + 4 scalars ----
        {
            float* ebase = out + ENC_OFF + (size_t)n0 * K_CB;
            #pragma unroll
            for (int r = 0; r < 8; r++) {
                const int sv = bi_r[r];
                float* rbase = ebase + (size_t)r * K_CB;
                #pragma unroll
                for (int m = lane; m < 127; m += 32) {
                    const int k = 3 + 4 * m;
                    float4 v;
                    v.x = (sv == k)     ? 1.0f : 0.0f;
                    v.y = (sv == k + 1) ? 1.0f : 0.0f;
                    v.z = (sv == k + 2) ? 1.0f : 0.0f;
                    v.w = (sv == k + 3) ? 1.0f : 0.0f;
                    __stcs((float4*)(rbase + k), v);   // 16B aligned (ENC_OFF odd + 3)
                }
                if (lane < 3)       rbase[lane] = (sv == lane) ? 1.0f : 0.0f;
                else if (lane == 3) rbase[511]  = (sv == 511)  ? 1.0f : 0.0f;
            }
        }

        // ---- q_out for own rows (x + (q - x)) + loss partial; 2 c per lane ----
        float s = 0.f;
        float* qbase = out + (size_t)bimg * (C_DIM * HW) + p0;
        #pragma unroll
        for (int cc = 0; cc < 2; cc++) {
            const int c = cc ? c1 : c0;
            float4 xa = *(const float4*)(slice + c * 8);
            float4 xb = *(const float4*)(slice + c * 8 + 4);
            const float* wrow = wT + c * WROW;
            float d0 = wrow[bi_r[0]] - xa.x;
            float d1 = wrow[bi_r[1]] - xa.y;
            float d2 = wrow[bi_r[2]] - xa.z;
            float d3 = wrow[bi_r[3]] - xa.w;
            float d4 = wrow[bi_r[4]] - xb.x;
            float d5 = wrow[bi_r[5]] - xb.y;
            float d6 = wrow[bi_r[6]] - xb.z;
            float d7 = wrow[bi_r[7]] - xb.w;
            float4 oa, ob;
            oa.x = xa.x + d0; oa.y = xa.y + d1; oa.z = xa.z + d2; oa.w = xa.w + d3;
            ob.x = xb.x + d4; ob.y = xb.y + d5; ob.z = xb.z + d6; ob.w = xb.w + d7;
            __stcs((float4*)(qbase + (size_t)c * HW),     oa);   // 32B-aligned block
            __stcs((float4*)(qbase + (size_t)c * HW + 4), ob);
            s = fmaf(d0, d0, s); s = fmaf(d1, d1, s);
            s = fmaf(d2, d2, s); s = fmaf(d3, d3, s);
            s = fmaf(d4, d4, s); s = fmaf(d5, d5, s);
            s = fmaf(d6, d6, s); s = fmaf(d7, d7, s);
        }
        #pragma unroll
        for (int off = 16; off > 0; off >>= 1) s += __shfl_xor_sync(0xffffffffu, s, off);
        if (lane == 0) g_lp[t * NWARP + warp] = s;

        __syncwarp();                  // slice reads done before next-iter prefetch reuse
        buf ^= 1;
    }
    CP_WAIT0();                        // drain dangling prefetch

    // ---- fused finish: last CTA computes loss + perplexity ----
    __syncthreads();
    __shared__ int s_last;
    if (tid == 0) {
        __threadfence();
        s_last = (atomicAdd(&g_done, 1) == NCTAS - 1);
    }
    __syncthreads();
    if (s_last) {
        if (tid == 0) g_done = 0;                 // reset for graph replay
        if (tid < B_DIM) {
            float s = 0.f;
            #pragma unroll
            for (int j = 0; j < 16; j++)          // tiles of batch, fixed order
                #pragma unroll
                for (int w = 0; w < NWARP; w++)   // warp partials, fixed order
                    s += g_lp[(tid * 16 + j) * NWARP + w];
            out[LOSS_OFF + tid] = 1.25f * (s * (1.0f / 65536.0f));
        }
        // perplexity over 512 bins with 256 threads: fold pairs then tree-reduce
        int h0 = g_hist[tid], h1 = g_hist[tid + 256];
        g_hist[tid] = 0; g_hist[tid + 256] = 0;   // restore zero invariant
        float pa = (float)h0 * (1.0f / 65536.0f);
        float pb = (float)h1 * (1.0f / 65536.0f);
        red[tid] = (-pa * logf(pa + 1e-10f)) + (-pb * logf(pb + 1e-10f));
        __syncthreads();
        #pragma unroll
        for (int off = 128; off > 0; off >>= 1) {
            if (tid < off) red[tid] += red[tid + off];
            __syncthreads();
        }
        if (tid == 0) out[PERP_OFF] = expf(red[0]);
    }
}

// ---------------- launch ----------------
extern "C" void kernel_launch(void* const* d_in, const int* in_sizes, int n_in,
                              void* d_out, int out_size)
{
    const float* inputs = (const float*)d_in[0];
    const float* weight = (const float*)d_in[1];
    float* out = (float*)d_out;

    if (out_size != OUT_TOTAL) return;

    cudaFuncSetAttribute(vq_all, cudaFuncAttributeMaxDynamicSharedMemorySize, SMEM_BYTES);

    vq_all<<<NCTAS, THREADS, SMEM_BYTES>>>(inputs, weight, out);
}